// round 2
// baseline (speedup 1.0000x reference)
#include <cuda_runtime.h>

#define F_IN   512
#define H_DIM  16
#define C_OUT  7
#define NMAX   100000
#define EMAX   3200000
#define TOTMAX (NMAX + EMAX)
#define CHUNK  512
#define NCMAX  ((NMAX + CHUNK - 1) / CHUNK)

// -------- scratch (static device globals; no runtime allocation) --------
static __device__ float g_h0[NMAX * H_DIM];
static __device__ float g_h1[NMAX * H_DIM];
static __device__ float g_invn[NMAX];
static __device__ int   g_counts[NMAX];
static __device__ int   g_cursor[NMAX];
static __device__ int   g_off[NMAX + 1];
static __device__ int   g_csr[TOTMAX];
static __device__ int   g_csums[NCMAX];

// ======================= lin1: h = relu(x @ W1^T + b1) =======================
// Warp layout: 16 k-lanes x 2 row-slots; each lane accumulates 4 full rows for
// its k -> no cross-lane reduction. W1 staged in shared (padded, stride 129
// float4). x read as float4, broadcast across the 16 k-lanes.
__global__ void k_lin1(const float* __restrict__ x, const float* __restrict__ W1,
                       const float* __restrict__ b1, float* __restrict__ h, int N)
{
    __shared__ float4 Ws[H_DIM * 129];
    const int tid = threadIdx.x;
    const float4* W14 = (const float4*)W1;
    for (int i = tid; i < H_DIM * 128; i += blockDim.x) {
        int k = i >> 7, j = i & 127;
        Ws[k * 129 + j] = W14[k * 128 + j];
    }
    __syncthreads();

    const int warp = tid >> 5, lane = tid & 31;
    const int k = lane & 15, slot = lane >> 4;
    const int row0 = (blockIdx.x * 8 + warp) * 8 + slot * 4;

    const int r0 = min(row0 + 0, N - 1);
    const int r1 = min(row0 + 1, N - 1);
    const int r2 = min(row0 + 2, N - 1);
    const int r3 = min(row0 + 3, N - 1);

    const float4* x4 = (const float4*)x;
    const float4* p0 = x4 + (size_t)r0 * 128;
    const float4* p1 = x4 + (size_t)r1 * 128;
    const float4* p2 = x4 + (size_t)r2 * 128;
    const float4* p3 = x4 + (size_t)r3 * 128;

    float a0 = 0.f, a1 = 0.f, a2 = 0.f, a3 = 0.f;
    #pragma unroll 4
    for (int j = 0; j < 128; j++) {
        float4 w = Ws[k * 129 + j];
        float4 v;
        v = p0[j]; a0 = fmaf(v.x, w.x, fmaf(v.y, w.y, fmaf(v.z, w.z, fmaf(v.w, w.w, a0))));
        v = p1[j]; a1 = fmaf(v.x, w.x, fmaf(v.y, w.y, fmaf(v.z, w.z, fmaf(v.w, w.w, a1))));
        v = p2[j]; a2 = fmaf(v.x, w.x, fmaf(v.y, w.y, fmaf(v.z, w.z, fmaf(v.w, w.w, a2))));
        v = p3[j]; a3 = fmaf(v.x, w.x, fmaf(v.y, w.y, fmaf(v.z, w.z, fmaf(v.w, w.w, a3))));
    }
    const float bk = b1[k];
    if (row0 + 0 < N) h[(row0 + 0) * H_DIM + k] = fmaxf(a0 + bk, 0.f);
    if (row0 + 1 < N) h[(row0 + 1) * H_DIM + k] = fmaxf(a1 + bk, 0.f);
    if (row0 + 2 < N) h[(row0 + 2) * H_DIM + k] = fmaxf(a2 + bk, 0.f);
    if (row0 + 3 < N) h[(row0 + 3) * H_DIM + k] = fmaxf(a3 + bk, 0.f);
}

// ======================= CSR build (dst-grouped, incl. self-loops) ===========
__global__ void k_count_init(int N)
{
    int i = blockIdx.x * blockDim.x + threadIdx.x;
    if (i < N) g_counts[i] = 1;   // self-loop
}

__global__ void k_count(const int* __restrict__ ei, int E)
{
    int e = blockIdx.x * blockDim.x + threadIdx.x;
    if (e < E) atomicAdd(&g_counts[ei[E + e]], 1);   // dst row
}

__global__ void k_csum(int N, int NC)
{
    int c = blockIdx.x * blockDim.x + threadIdx.x;
    if (c >= NC) return;
    int b = c * CHUNK, e = min(b + CHUNK, N);
    int s = 0;
    for (int i = b; i < e; i++) s += g_counts[i];
    g_csums[c] = s;
}

__global__ void k_scan(int NC)
{
    if (blockIdx.x == 0 && threadIdx.x == 0) {
        int run = 0;
        for (int c = 0; c < NC; c++) { int t = g_csums[c]; g_csums[c] = run; run += t; }
    }
}

__global__ void k_cscan(int N, int NC)
{
    int c = blockIdx.x * blockDim.x + threadIdx.x;
    if (c >= NC) return;
    int b = c * CHUNK, e = min(b + CHUNK, N);
    int run = g_csums[c];
    for (int i = b; i < e; i++) {
        g_off[i] = run; g_cursor[i] = run;
        run += g_counts[i];
    }
    if (c == NC - 1) g_off[N] = run;
}

__global__ void k_scatter(const int* __restrict__ ei, int E, int N)
{
    int t = blockIdx.x * blockDim.x + threadIdx.x;
    if (t >= E + N) return;
    int s, d;
    if (t < E) { s = ei[t]; d = ei[E + t]; }
    else       { s = t - E; d = s; }
    int pos = atomicAdd(&g_cursor[d], 1);
    g_csr[pos] = s;
}

// ======================= per-node inverse norm ===============================
__global__ void k_norm(const float* __restrict__ h, int N)
{
    int i = blockIdx.x * blockDim.x + threadIdx.x;
    if (i >= N) return;
    const float4* h4 = (const float4*)h;
    float ss = 0.f;
    #pragma unroll
    for (int t = 0; t < 4; t++) {
        float4 v = h4[i * 4 + t];
        ss = fmaf(v.x, v.x, fmaf(v.y, v.y, fmaf(v.z, v.z, fmaf(v.w, v.w, ss))));
    }
    g_invn[i] = 1.0f / fmaxf(sqrtf(ss), 1e-12f);
}

// ======================= fused AGNN layer (online softmax) ===================
// 8 lanes per dst node; each lane keeps running (m, s, num[16]); butterfly
// combine within the octet; lane 0 writes the row.
__global__ void k_agnn(const float* __restrict__ hin, float* __restrict__ hout,
                       const float* __restrict__ betap, int use_beta, int N)
{
    int gid = blockIdx.x * blockDim.x + threadIdx.x;
    int node = gid >> 3;
    int sub  = gid & 7;
    int store_ok = (node < N);
    if (node >= N) node = N - 1;   // clamp: keep all lanes alive for shuffles

    const float beta = use_beta ? betap[0] : 1.0f;
    const float4* h4 = (const float4*)hin;

    float hd[16];
    #pragma unroll
    for (int t = 0; t < 4; t++) {
        float4 v = h4[node * 4 + t];
        hd[t * 4 + 0] = v.x; hd[t * 4 + 1] = v.y; hd[t * 4 + 2] = v.z; hd[t * 4 + 3] = v.w;
    }
    const float cd = beta * g_invn[node];
    const int beg = g_off[node], end = g_off[node + 1];

    float m = -1e30f, s = 0.f;
    float n[16];
    #pragma unroll
    for (int q = 0; q < 16; q++) n[q] = 0.f;

    for (int i = beg + sub; i < end; i += 8) {
        const int src = g_csr[i];
        float hs[16];
        #pragma unroll
        for (int t = 0; t < 4; t++) {
            float4 v = h4[src * 4 + t];
            hs[t * 4 + 0] = v.x; hs[t * 4 + 1] = v.y; hs[t * 4 + 2] = v.z; hs[t * 4 + 3] = v.w;
        }
        float dot = 0.f;
        #pragma unroll
        for (int q = 0; q < 16; q++) dot = fmaf(hd[q], hs[q], dot);
        const float l  = cd * g_invn[src] * dot;
        const float nm = fmaxf(m, l);
        const float sc = __expf(m - nm);
        const float w  = __expf(l - nm);
        s = fmaf(s, sc, w);
        #pragma unroll
        for (int q = 0; q < 16; q++) n[q] = fmaf(n[q], sc, w * hs[q]);
        m = nm;
    }

    // octet butterfly combine
    #pragma unroll
    for (int o = 4; o > 0; o >>= 1) {
        const float m2 = __shfl_xor_sync(0xffffffffu, m, o);
        const float s2 = __shfl_xor_sync(0xffffffffu, s, o);
        const float nm = fmaxf(m, m2);
        const float a  = __expf(m - nm);
        const float b  = __expf(m2 - nm);
        s = s * a + s2 * b;
        #pragma unroll
        for (int q = 0; q < 16; q++) {
            const float n2 = __shfl_xor_sync(0xffffffffu, n[q], o);
            n[q] = n[q] * a + n2 * b;
        }
        m = nm;
    }

    if (sub == 0 && store_ok) {
        const float is = 1.0f / s;
        float4* o4 = (float4*)hout;
        o4[node * 4 + 0] = make_float4(n[0]  * is, n[1]  * is, n[2]  * is, n[3]  * is);
        o4[node * 4 + 1] = make_float4(n[4]  * is, n[5]  * is, n[6]  * is, n[7]  * is);
        o4[node * 4 + 2] = make_float4(n[8]  * is, n[9]  * is, n[10] * is, n[11] * is);
        o4[node * 4 + 3] = make_float4(n[12] * is, n[13] * is, n[14] * is, n[15] * is);
    }
}

// ======================= classify + log_softmax ==============================
__global__ void k_out(const float* __restrict__ h, const float* __restrict__ W2,
                      const float* __restrict__ b2, float* __restrict__ out, int N)
{
    __shared__ float sW[C_OUT * H_DIM];
    __shared__ float sb[C_OUT];
    const int tid = threadIdx.x;
    if (tid < C_OUT * H_DIM) sW[tid] = W2[tid];
    if (tid < C_OUT) sb[tid] = b2[tid];
    __syncthreads();

    const int i = blockIdx.x * blockDim.x + tid;
    if (i >= N) return;

    float hv[16];
    const float4* h4 = (const float4*)h;
    #pragma unroll
    for (int t = 0; t < 4; t++) {
        float4 v = h4[i * 4 + t];
        hv[t * 4 + 0] = v.x; hv[t * 4 + 1] = v.y; hv[t * 4 + 2] = v.z; hv[t * 4 + 3] = v.w;
    }
    float lg[C_OUT];
    #pragma unroll
    for (int c = 0; c < C_OUT; c++) {
        float acc = sb[c];
        #pragma unroll
        for (int q = 0; q < 16; q++) acc = fmaf(hv[q], sW[c * 16 + q], acc);
        lg[c] = acc;
    }
    float mx = lg[0];
    #pragma unroll
    for (int c = 1; c < C_OUT; c++) mx = fmaxf(mx, lg[c]);
    float ssum = 0.f;
    #pragma unroll
    for (int c = 0; c < C_OUT; c++) ssum += __expf(lg[c] - mx);
    const float lse = mx + __logf(ssum);
    #pragma unroll
    for (int c = 0; c < C_OUT; c++) out[i * C_OUT + c] = lg[c] - lse;
}

// ======================= launch ==============================================
extern "C" void kernel_launch(void* const* d_in, const int* in_sizes, int n_in,
                              void* d_out, int out_size)
{
    const float* x     = (const float*)d_in[0];
    const int*   ei    = (const int*)d_in[1];
    const float* W1    = (const float*)d_in[2];
    const float* b1    = (const float*)d_in[3];
    const float* beta2 = (const float*)d_in[4];
    const float* beta3 = (const float*)d_in[5];
    const float* beta4 = (const float*)d_in[6];
    const float* W2    = (const float*)d_in[7];
    const float* b2    = (const float*)d_in[8];
    float* out = (float*)d_out;

    const int N = in_sizes[0] / F_IN;
    const int E = in_sizes[1] / 2;
    const int NC = (N + CHUNK - 1) / CHUNK;

    float *hA, *hB;
    cudaGetSymbolAddress((void**)&hA, g_h0);
    cudaGetSymbolAddress((void**)&hB, g_h1);

    // lin1
    k_lin1<<<(N + 63) / 64, 256>>>(x, W1, b1, hA, N);

    // CSR build (independent of lin1; serialized on stream)
    k_count_init<<<(N + 255) / 256, 256>>>(N);
    k_count<<<(E + 255) / 256, 256>>>(ei, E);
    k_csum<<<(NC + 255) / 256, 256>>>(N, NC);
    k_scan<<<1, 32>>>(NC);
    k_cscan<<<(NC + 255) / 256, 256>>>(N, NC);
    k_scatter<<<(E + N + 255) / 256, 256>>>(ei, E, N);

    // 4 AGNN layers (layer 0: beta fixed at 1.0)
    const float* betas[4] = {nullptr, beta2, beta3, beta4};
    float* cur = hA; float* nxt = hB;
    for (int l = 0; l < 4; l++) {
        k_norm<<<(N + 255) / 256, 256>>>(cur, N);
        k_agnn<<<(N * 8 + 255) / 256, 256>>>(cur, nxt, betas[l], l > 0 ? 1 : 0, N);
        float* t = cur; cur = nxt; nxt = t;
    }

    // classify + log_softmax
    k_out<<<(N + 255) / 256, 256>>>(cur, W2, b2, out, N);
}

// round 5
// speedup vs baseline: 1.6222x; 1.6222x over previous
#include <cuda_runtime.h>

#define F_IN   512
#define H_DIM  16
#define C_OUT  7
#define NMAX   100000
#define EMAX   3200000
#define TOTMAX (NMAX + EMAX)
#define CHUNK  512
#define NCMAX  ((NMAX + CHUNK - 1) / CHUNK)

// -------- scratch (static device globals; no runtime allocation) --------
static __device__ float g_h0[NMAX * H_DIM];
static __device__ float g_h1[NMAX * H_DIM];
static __device__ float g_invnA[NMAX];
static __device__ float g_invnB[NMAX];
static __device__ int   g_counts[NMAX];
static __device__ int   g_cursor[NMAX];
static __device__ int   g_off[NMAX + 1];
static __device__ int   g_csr[TOTMAX];
static __device__ int   g_csums[NCMAX];

// ======================= lin1: h = relu(x @ W1^T + b1), fused ||h|| ==========
// Warp layout: 16 k-lanes x 2 row-slots; each lane accumulates 4 full rows for
// its k. After relu, a 4-step butterfly across the 16 k-lanes produces the
// row sum-of-squares -> writes g_invnA too (no separate norm kernel).
__global__ void k_lin1(const float* __restrict__ x, const float* __restrict__ W1,
                       const float* __restrict__ b1, float* __restrict__ h,
                       float* __restrict__ invn, int N)
{
    __shared__ float4 Ws[H_DIM * 129];
    const int tid = threadIdx.x;
    const float4* W14 = (const float4*)W1;
    for (int i = tid; i < H_DIM * 128; i += blockDim.x) {
        int k = i >> 7, j = i & 127;
        Ws[k * 129 + j] = W14[k * 128 + j];
    }
    __syncthreads();

    const int warp = tid >> 5, lane = tid & 31;
    const int k = lane & 15, slot = lane >> 4;
    const int row0 = (blockIdx.x * 8 + warp) * 8 + slot * 4;

    const int r0 = min(row0 + 0, N - 1);
    const int r1 = min(row0 + 1, N - 1);
    const int r2 = min(row0 + 2, N - 1);
    const int r3 = min(row0 + 3, N - 1);

    const float4* x4 = (const float4*)x;
    const float4* p0 = x4 + (size_t)r0 * 128;
    const float4* p1 = x4 + (size_t)r1 * 128;
    const float4* p2 = x4 + (size_t)r2 * 128;
    const float4* p3 = x4 + (size_t)r3 * 128;

    float a0 = 0.f, a1 = 0.f, a2 = 0.f, a3 = 0.f;
    #pragma unroll 4
    for (int j = 0; j < 128; j++) {
        float4 w = Ws[k * 129 + j];
        float4 v;
        v = p0[j]; a0 = fmaf(v.x, w.x, fmaf(v.y, w.y, fmaf(v.z, w.z, fmaf(v.w, w.w, a0))));
        v = p1[j]; a1 = fmaf(v.x, w.x, fmaf(v.y, w.y, fmaf(v.z, w.z, fmaf(v.w, w.w, a1))));
        v = p2[j]; a2 = fmaf(v.x, w.x, fmaf(v.y, w.y, fmaf(v.z, w.z, fmaf(v.w, w.w, a2))));
        v = p3[j]; a3 = fmaf(v.x, w.x, fmaf(v.y, w.y, fmaf(v.z, w.z, fmaf(v.w, w.w, a3))));
    }
    const float bk = b1[k];
    const float v0 = fmaxf(a0 + bk, 0.f);
    const float v1 = fmaxf(a1 + bk, 0.f);
    const float v2 = fmaxf(a2 + bk, 0.f);
    const float v3 = fmaxf(a3 + bk, 0.f);

    if (row0 + 0 < N) h[(row0 + 0) * H_DIM + k] = v0;
    if (row0 + 1 < N) h[(row0 + 1) * H_DIM + k] = v1;
    if (row0 + 2 < N) h[(row0 + 2) * H_DIM + k] = v2;
    if (row0 + 3 < N) h[(row0 + 3) * H_DIM + k] = v3;

    // sum of squares across the 16 k-lanes (xor offsets < 16 stay in-half)
    float s0 = v0 * v0, s1 = v1 * v1, s2 = v2 * v2, s3 = v3 * v3;
    #pragma unroll
    for (int o = 1; o < 16; o <<= 1) {
        s0 += __shfl_xor_sync(0xffffffffu, s0, o);
        s1 += __shfl_xor_sync(0xffffffffu, s1, o);
        s2 += __shfl_xor_sync(0xffffffffu, s2, o);
        s3 += __shfl_xor_sync(0xffffffffu, s3, o);
    }
    if (k == 0) {
        if (row0 + 0 < N) invn[row0 + 0] = 1.0f / fmaxf(sqrtf(s0), 1e-12f);
        if (row0 + 1 < N) invn[row0 + 1] = 1.0f / fmaxf(sqrtf(s1), 1e-12f);
        if (row0 + 2 < N) invn[row0 + 2] = 1.0f / fmaxf(sqrtf(s2), 1e-12f);
        if (row0 + 3 < N) invn[row0 + 3] = 1.0f / fmaxf(sqrtf(s3), 1e-12f);
    }
}

// ======================= CSR build (dst-grouped, incl. self-loops) ===========
__global__ void k_count_init(int N)
{
    int i = blockIdx.x * blockDim.x + threadIdx.x;
    if (i < N) g_counts[i] = 1;   // self-loop
}

// 4 edges per thread via int4 on the dst half
__global__ void k_count(const int* __restrict__ ei, int E)
{
    int t = blockIdx.x * blockDim.x + threadIdx.x;
    int e = t * 4;
    if (e + 3 < E) {
        int4 d = *(const int4*)(ei + E + e);
        atomicAdd(&g_counts[d.x], 1);
        atomicAdd(&g_counts[d.y], 1);
        atomicAdd(&g_counts[d.z], 1);
        atomicAdd(&g_counts[d.w], 1);
    } else {
        for (int j = e; j < E; j++) atomicAdd(&g_counts[ei[E + j]], 1);
    }
}

// one block per chunk: tree-reduce 512 counts -> g_csums[chunk]
__global__ void k_csum(int N)
{
    const int c = blockIdx.x;
    const int tid = threadIdx.x;           // 256 threads
    const int i = c * CHUNK + tid;
    int s = 0;
    if (i < N) s = g_counts[i];
    if (i + 256 < N && tid + 256 < CHUNK) s += g_counts[i + 256];
    #pragma unroll
    for (int o = 16; o > 0; o >>= 1) s += __shfl_xor_sync(0xffffffffu, s, o);
    __shared__ int ws[8];
    if ((tid & 31) == 0) ws[tid >> 5] = s;
    __syncthreads();
    if (tid < 8) {
        int v = ws[tid];
        #pragma unroll
        for (int o = 4; o > 0; o >>= 1) v += __shfl_xor_sync(0x000000ffu, v, o);
        if (tid == 0) g_csums[c] = v;
    }
}

// single block exclusive scan over NC (<=256) chunk sums
__global__ void k_scan(int NC)
{
    const int tid = threadIdx.x;           // 256 threads
    const int lane = tid & 31, w = tid >> 5;
    int v = (tid < NC) ? g_csums[tid] : 0;
    int x = v;
    #pragma unroll
    for (int o = 1; o < 32; o <<= 1) {
        int t = __shfl_up_sync(0xffffffffu, x, o);
        if (lane >= o) x += t;
    }
    __shared__ int wsum[8];
    if (lane == 31) wsum[w] = x;
    __syncthreads();
    if (tid < 8) {
        int y = wsum[tid];
        #pragma unroll
        for (int o = 1; o < 8; o <<= 1) {
            int t = __shfl_up_sync(0x000000ffu, y, o);
            if (tid >= o) y += t;
        }
        wsum[tid] = y;
    }
    __syncthreads();
    const int incl = x + (w ? wsum[w - 1] : 0);
    if (tid < NC) g_csums[tid] = incl - v;   // exclusive
}

// one block (512 thr) per chunk: block-scan counts, add chunk base, emit offsets
__global__ void k_cscan(int N)
{
    const int c = blockIdx.x;
    const int tid = threadIdx.x;           // 512 threads
    const int i = c * CHUNK + tid;
    const int lane = tid & 31, w = tid >> 5;   // 16 warps
    const int v = (i < N) ? g_counts[i] : 0;
    int x = v;
    #pragma unroll
    for (int o = 1; o < 32; o <<= 1) {
        int t = __shfl_up_sync(0xffffffffu, x, o);
        if (lane >= o) x += t;
    }
    __shared__ int wsum[16];
    if (lane == 31) wsum[w] = x;
    __syncthreads();
    if (tid < 16) {
        int y = wsum[tid];
        #pragma unroll
        for (int o = 1; o < 16; o <<= 1) {
            int t = __shfl_up_sync(0x0000ffffu, y, o);
            if (tid >= o) y += t;
        }
        wsum[tid] = y;
    }
    __syncthreads();
    const int excl = x - v + (w ? wsum[w - 1] : 0);
    const int off = g_csums[c] + excl;
    if (i < N) {
        g_off[i] = off;
        g_cursor[i] = off;
        if (i == N - 1) g_off[N] = off + v;
    }
}

__global__ void k_scatter(const int* __restrict__ ei, int E, int N)
{
    int t = blockIdx.x * blockDim.x + threadIdx.x;
    if (t >= E + N) return;
    int s, d;
    if (t < E) { s = ei[t]; d = ei[E + t]; }
    else       { s = t - E; d = s; }
    int pos = atomicAdd(&g_cursor[d], 1);
    g_csr[pos] = s;
}

// ======================= fused AGNN layer (online softmax + next invn) =======
// 8 lanes per dst node; each lane keeps running (m, s, num[16]) with a
// single-expf update per edge; butterfly combine within the octet; lane 0
// writes the row and the next layer's invn.
__global__ void k_agnn(const float* __restrict__ hin, float* __restrict__ hout,
                       const float* __restrict__ invn_in, float* __restrict__ invn_out,
                       const float* __restrict__ betap, int use_beta, int N)
{
    int gid = blockIdx.x * blockDim.x + threadIdx.x;
    int node = gid >> 3;
    int sub  = gid & 7;
    int store_ok = (node < N);
    if (node >= N) node = N - 1;   // clamp: keep all lanes alive for shuffles

    const float beta = use_beta ? betap[0] : 1.0f;
    const float4* h4 = (const float4*)hin;

    float hd[16];
    #pragma unroll
    for (int t = 0; t < 4; t++) {
        float4 v = h4[node * 4 + t];
        hd[t * 4 + 0] = v.x; hd[t * 4 + 1] = v.y; hd[t * 4 + 2] = v.z; hd[t * 4 + 3] = v.w;
    }
    const float cd = beta * invn_in[node];
    const int beg = g_off[node], end = g_off[node + 1];

    float m = -1e30f, s = 0.f;
    float n[16];
    #pragma unroll
    for (int q = 0; q < 16; q++) n[q] = 0.f;

    for (int i = beg + sub; i < end; i += 8) {
        const int src = g_csr[i];
        float hs[16];
        #pragma unroll
        for (int t = 0; t < 4; t++) {
            float4 v = h4[src * 4 + t];
            hs[t * 4 + 0] = v.x; hs[t * 4 + 1] = v.y; hs[t * 4 + 2] = v.z; hs[t * 4 + 3] = v.w;
        }
        float dot = 0.f;
        #pragma unroll
        for (int q = 0; q < 16; q++) dot = fmaf(hd[q], hs[q], dot);
        const float l = cd * invn_in[src] * dot;
        if (l > m) {
            // new running max: rescale old state, weight of this edge = 1
            const float sc = __expf(m - l);
            s = fmaf(s, sc, 1.0f);
            #pragma unroll
            for (int q = 0; q < 16; q++) n[q] = fmaf(n[q], sc, hs[q]);
            m = l;
        } else {
            const float w = __expf(l - m);
            s += w;
            #pragma unroll
            for (int q = 0; q < 16; q++) n[q] = fmaf(w, hs[q], n[q]);
        }
    }

    // octet butterfly combine
    #pragma unroll
    for (int o = 4; o > 0; o >>= 1) {
        const float m2 = __shfl_xor_sync(0xffffffffu, m, o);
        const float s2 = __shfl_xor_sync(0xffffffffu, s, o);
        const float nm = fmaxf(m, m2);
        const float a  = __expf(m - nm);
        const float b  = __expf(m2 - nm);
        s = s * a + s2 * b;
        #pragma unroll
        for (int q = 0; q < 16; q++) {
            const float n2 = __shfl_xor_sync(0xffffffffu, n[q], o);
            n[q] = n[q] * a + n2 * b;
        }
        m = nm;
    }

    if (sub == 0 && store_ok) {
        const float is = 1.0f / s;
        float v[16];
        float ss = 0.f;
        #pragma unroll
        for (int q = 0; q < 16; q++) { v[q] = n[q] * is; ss = fmaf(v[q], v[q], ss); }
        float4* o4 = (float4*)hout;
        o4[node * 4 + 0] = make_float4(v[0],  v[1],  v[2],  v[3]);
        o4[node * 4 + 1] = make_float4(v[4],  v[5],  v[6],  v[7]);
        o4[node * 4 + 2] = make_float4(v[8],  v[9],  v[10], v[11]);
        o4[node * 4 + 3] = make_float4(v[12], v[13], v[14], v[15]);
        invn_out[node] = 1.0f / fmaxf(sqrtf(ss), 1e-12f);
    }
}

// ======================= classify + log_softmax ==============================
__global__ void k_out(const float* __restrict__ h, const float* __restrict__ W2,
                      const float* __restrict__ b2, float* __restrict__ out, int N)
{
    __shared__ float sW[C_OUT * H_DIM];
    __shared__ float sb[C_OUT];
    const int tid = threadIdx.x;
    if (tid < C_OUT * H_DIM) sW[tid] = W2[tid];
    if (tid < C_OUT) sb[tid] = b2[tid];
    __syncthreads();

    const int i = blockIdx.x * blockDim.x + tid;
    if (i >= N) return;

    float hv[16];
    const float4* h4 = (const float4*)h;
    #pragma unroll
    for (int t = 0; t < 4; t++) {
        float4 v = h4[i * 4 + t];
        hv[t * 4 + 0] = v.x; hv[t * 4 + 1] = v.y; hv[t * 4 + 2] = v.z; hv[t * 4 + 3] = v.w;
    }
    float lg[C_OUT];
    #pragma unroll
    for (int c = 0; c < C_OUT; c++) {
        float acc = sb[c];
        #pragma unroll
        for (int q = 0; q < 16; q++) acc = fmaf(hv[q], sW[c * 16 + q], acc);
        lg[c] = acc;
    }
    float mx = lg[0];
    #pragma unroll
    for (int c = 1; c < C_OUT; c++) mx = fmaxf(mx, lg[c]);
    float ssum = 0.f;
    #pragma unroll
    for (int c = 0; c < C_OUT; c++) ssum += __expf(lg[c] - mx);
    const float lse = mx + __logf(ssum);
    #pragma unroll
    for (int c = 0; c < C_OUT; c++) out[i * C_OUT + c] = lg[c] - lse;
}

// ======================= launch ==============================================
extern "C" void kernel_launch(void* const* d_in, const int* in_sizes, int n_in,
                              void* d_out, int out_size)
{
    const float* x     = (const float*)d_in[0];
    const int*   ei    = (const int*)d_in[1];
    const float* W1    = (const float*)d_in[2];
    const float* b1    = (const float*)d_in[3];
    const float* beta2 = (const float*)d_in[4];
    const float* beta3 = (const float*)d_in[5];
    const float* beta4 = (const float*)d_in[6];
    const float* W2    = (const float*)d_in[7];
    const float* b2    = (const float*)d_in[8];
    float* out = (float*)d_out;

    const int N = in_sizes[0] / F_IN;
    const int E = in_sizes[1] / 2;
    const int NC = (N + CHUNK - 1) / CHUNK;

    float *hA, *hB, *inA, *inB;
    cudaGetSymbolAddress((void**)&hA, g_h0);
    cudaGetSymbolAddress((void**)&hB, g_h1);
    cudaGetSymbolAddress((void**)&inA, g_invnA);
    cudaGetSymbolAddress((void**)&inB, g_invnB);

    // lin1 (+ invn of h)
    k_lin1<<<(N + 63) / 64, 256>>>(x, W1, b1, hA, inA, N);

    // CSR build
    k_count_init<<<(N + 255) / 256, 256>>>(N);
    k_count<<<((E + 3) / 4 + 255) / 256, 256>>>(ei, E);
    k_csum<<<NC, 256>>>(N);
    k_scan<<<1, 256>>>(NC);
    k_cscan<<<NC, 512>>>(N);
    k_scatter<<<(E + N + 255) / 256, 256>>>(ei, E, N);

    // 4 AGNN layers (layer 0: beta fixed at 1.0)
    const float* betas[4] = {nullptr, beta2, beta3, beta4};
    float* cur = hA; float* nxt = hB;
    float* icur = inA; float* inxt = inB;
    for (int l = 0; l < 4; l++) {
        k_agnn<<<(N * 8 + 255) / 256, 256>>>(cur, nxt, icur, inxt, betas[l], l > 0 ? 1 : 0, N);
        float* t = cur; cur = nxt; nxt = t;
        t = icur; icur = inxt; inxt = t;
    }

    // classify + log_softmax
    k_out<<<(N + 255) / 256, 256>>>(cur, W2, b2, out, N);
}